// round 2
// baseline (speedup 1.0000x reference)
#include <cuda_runtime.h>
#include <math.h>

// Output: spikes[t, b, n] = (t == spike_time[b,n]) ? 1.f : 0.f
// spike_time = floor(sigmoid(x) * (T-1)) with XLA-bit-exact f32 sigmoid:
//   XLA logistic expansion: s = 1 / (1 + exp(-x)), exp = libdevice __nv_expf,
//   every op rounded in f32. Then f32 multiply by (T-1), floorf, int cast.
//
// Store strategy: each thread owns 4 consecutive (b,n) elements (float4 lane),
// writes T float4 zero-stores (stride B*N floats), then overwrites its 4
// spike positions with 1.0f (same-thread same-address stores are ordered).

extern "C" __device__ float __nv_expf(float);  // libdevice precise expf

__device__ __forceinline__ int xla_spike_time(float x, float tm1) {
    float e = __nv_expf(-x);                       // f32 exp(-x), libdevice
    float s = __fdiv_rn(1.0f, __fadd_rn(1.0f, e)); // 1/(1+e), f32 rn
    return (int)floorf(__fmul_rn(s, tm1));         // floor(s*(T-1))
}

template <int T>
__global__ void __launch_bounds__(256)
temporal_encode_kernel(const float4* __restrict__ in,
                       float* __restrict__ out,
                       int BN4)  // B*N/4
{
    int idx = blockIdx.x * blockDim.x + threadIdx.x;
    if (idx >= BN4) return;

    float4 x = in[idx];
    const float tm1 = (float)(T - 1);
    int st0 = xla_spike_time(x.x, tm1);
    int st1 = xla_spike_time(x.y, tm1);
    int st2 = xla_spike_time(x.z, tm1);
    int st3 = xla_spike_time(x.w, tm1);

    // Zero-fill this lane's column across all T timesteps.
    float4* p = reinterpret_cast<float4*>(out) + idx;
    const float4 z = make_float4(0.f, 0.f, 0.f, 0.f);
    const size_t stride4 = (size_t)BN4;  // float4 units == B*N floats
#pragma unroll
    for (int t = 0; t < T; t++) {
        p[(size_t)t * stride4] = z;
    }

    // Scatter the ones (overwrite; same thread, same address -> ordered).
    const size_t BN = (size_t)BN4 * 4;
    const size_t base = (size_t)idx * 4;
    out[(size_t)st0 * BN + base + 0] = 1.0f;
    out[(size_t)st1 * BN + base + 1] = 1.0f;
    out[(size_t)st2 * BN + base + 2] = 1.0f;
    out[(size_t)st3 * BN + base + 3] = 1.0f;
}

// Generic-T fallback
__global__ void __launch_bounds__(256)
temporal_encode_kernel_dyn(const float4* __restrict__ in,
                           float* __restrict__ out,
                           int BN4, int T)
{
    int idx = blockIdx.x * blockDim.x + threadIdx.x;
    if (idx >= BN4) return;

    float4 x = in[idx];
    const float tm1 = (float)(T - 1);
    int st0 = xla_spike_time(x.x, tm1);
    int st1 = xla_spike_time(x.y, tm1);
    int st2 = xla_spike_time(x.z, tm1);
    int st3 = xla_spike_time(x.w, tm1);

    float4* p = reinterpret_cast<float4*>(out) + idx;
    const float4 z = make_float4(0.f, 0.f, 0.f, 0.f);
    const size_t stride4 = (size_t)BN4;
#pragma unroll 4
    for (int t = 0; t < T; t++) {
        p[(size_t)t * stride4] = z;
    }

    const size_t BN = (size_t)BN4 * 4;
    const size_t base = (size_t)idx * 4;
    out[(size_t)st0 * BN + base + 0] = 1.0f;
    out[(size_t)st1 * BN + base + 1] = 1.0f;
    out[(size_t)st2 * BN + base + 2] = 1.0f;
    out[(size_t)st3 * BN + base + 3] = 1.0f;
}

extern "C" void kernel_launch(void* const* d_in, const int* in_sizes, int n_in,
                              void* d_out, int out_size)
{
    const float* in = (const float*)d_in[0];
    float* out = (float*)d_out;

    const int BN = in_sizes[0];   // B * N = 1048576
    const int T = out_size / BN;  // timesteps = 100
    const int BN4 = BN / 4;

    const int threads = 256;
    const int blocks = (BN4 + threads - 1) / threads;

    if (T == 100) {
        temporal_encode_kernel<100><<<blocks, threads>>>(
            (const float4*)in, out, BN4);
    } else {
        temporal_encode_kernel_dyn<<<blocks, threads>>>(
            (const float4*)in, out, BN4, T);
    }
}

// round 3
// speedup vs baseline: 1.1565x; 1.1565x over previous
#include <cuda_runtime.h>
#include <math.h>

// Output: spikes[t, b, n] = (t == spike_time[b,n]) ? 1.f : 0.f
// spike_time = floor(sigmoid(x) * (T-1)) with XLA-bit-exact f32 sigmoid:
//   s = 1 / (1 + __nv_expf(-x)), every op f32-rounded (verified rel_err==0).
//
// Single fused pass: each thread owns 4 consecutive (b,n) columns. For each
// of the T planes it builds the float4 (compare-select against the 4 spike
// times) and streams it with one STG.128 (__stcs, evict-first). Every output
// byte is written exactly once, perfectly coalesced -> pure 419MB write.

extern "C" __device__ float __nv_expf(float);  // libdevice precise expf

__device__ __forceinline__ int xla_spike_time(float x, float tm1) {
    float e = __nv_expf(-x);                       // f32 exp(-x), libdevice
    float s = __fdiv_rn(1.0f, __fadd_rn(1.0f, e)); // 1/(1+e), f32 rn
    return (int)floorf(__fmul_rn(s, tm1));         // floor(s*(T-1))
}

template <int T>
__global__ void __launch_bounds__(256)
temporal_encode_fused(const float4* __restrict__ in,
                      float4* __restrict__ out,
                      int BN4)  // B*N/4
{
    int idx = blockIdx.x * blockDim.x + threadIdx.x;
    if (idx >= BN4) return;

    float4 x = in[idx];
    const float tm1 = (float)(T - 1);
    int st0 = xla_spike_time(x.x, tm1);
    int st1 = xla_spike_time(x.y, tm1);
    int st2 = xla_spike_time(x.z, tm1);
    int st3 = xla_spike_time(x.w, tm1);

    float4* p = out + idx;
    const size_t stride4 = (size_t)BN4;  // float4 units == B*N floats
#pragma unroll
    for (int t = 0; t < T; t++) {
        float4 v;
        v.x = (st0 == t) ? 1.0f : 0.0f;
        v.y = (st1 == t) ? 1.0f : 0.0f;
        v.z = (st2 == t) ? 1.0f : 0.0f;
        v.w = (st3 == t) ? 1.0f : 0.0f;
        __stcs(p, v);          // streaming store, evict-first
        p += stride4;
    }
}

// Generic-T fallback
__global__ void __launch_bounds__(256)
temporal_encode_fused_dyn(const float4* __restrict__ in,
                          float4* __restrict__ out,
                          int BN4, int T)
{
    int idx = blockIdx.x * blockDim.x + threadIdx.x;
    if (idx >= BN4) return;

    float4 x = in[idx];
    const float tm1 = (float)(T - 1);
    int st0 = xla_spike_time(x.x, tm1);
    int st1 = xla_spike_time(x.y, tm1);
    int st2 = xla_spike_time(x.z, tm1);
    int st3 = xla_spike_time(x.w, tm1);

    float4* p = out + idx;
    const size_t stride4 = (size_t)BN4;
#pragma unroll 4
    for (int t = 0; t < T; t++) {
        float4 v;
        v.x = (st0 == t) ? 1.0f : 0.0f;
        v.y = (st1 == t) ? 1.0f : 0.0f;
        v.z = (st2 == t) ? 1.0f : 0.0f;
        v.w = (st3 == t) ? 1.0f : 0.0f;
        __stcs(p, v);
        p += stride4;
    }
}

extern "C" void kernel_launch(void* const* d_in, const int* in_sizes, int n_in,
                              void* d_out, int out_size)
{
    const float* in = (const float*)d_in[0];
    float4* out = (float4*)d_out;

    const int BN = in_sizes[0];   // B * N = 1048576
    const int T = out_size / BN;  // timesteps = 100
    const int BN4 = BN / 4;

    const int threads = 256;
    const int blocks = (BN4 + threads - 1) / threads;

    if (T == 100) {
        temporal_encode_fused<100><<<blocks, threads>>>(
            (const float4*)in, out, BN4);
    } else {
        temporal_encode_fused_dyn<<<blocks, threads>>>(
            (const float4*)in, out, BN4, T);
    }
}

// round 4
// speedup vs baseline: 1.2642x; 1.0931x over previous
#include <cuda_runtime.h>
#include <math.h>

// Output: spikes[t, b, n] = (t == spike_time[b,n]) ? 1.f : 0.f
// spike_time = floor(sigmoid(x) * (T-1)) with XLA-bit-exact f32 sigmoid:
//   s = 1 / (1 + __nv_expf(-x)), every op f32-rounded (verified rel_err==0).
//
// R4: T-split by 4. grid = (BN4/256, 4). Each thread computes its 4 spike
// times (recomputed per split; 4 exps extra, trivial) and streams 25 planes
// of float4 compare-select values with __stcs. 4096 blocks -> 8 resident
// blocks/SM (64 warps, full occupancy) and fine-grained tail.

extern "C" __device__ float __nv_expf(float);  // libdevice precise expf

__device__ __forceinline__ int xla_spike_time(float x, float tm1) {
    float e = __nv_expf(-x);                       // f32 exp(-x), libdevice
    float s = __fdiv_rn(1.0f, __fadd_rn(1.0f, e)); // 1/(1+e), f32 rn
    return (int)floorf(__fmul_rn(s, tm1));         // floor(s*(T-1))
}

template <int T, int TSPLIT>
__global__ void __launch_bounds__(256)
temporal_encode_fused(const float4* __restrict__ in,
                      float4* __restrict__ out,
                      int BN4)  // B*N/4
{
    int idx = blockIdx.x * blockDim.x + threadIdx.x;
    if (idx >= BN4) return;

    float4 x = in[idx];
    const float tm1 = (float)(T - 1);
    int st0 = xla_spike_time(x.x, tm1);
    int st1 = xla_spike_time(x.y, tm1);
    int st2 = xla_spike_time(x.z, tm1);
    int st3 = xla_spike_time(x.w, tm1);

    constexpr int TCHUNK = T / TSPLIT;   // 25
    const int t0 = blockIdx.y * TCHUNK;

    const size_t stride4 = (size_t)BN4;  // float4 units == B*N floats
    float4* p = out + (size_t)t0 * stride4 + idx;
#pragma unroll
    for (int i = 0; i < TCHUNK; i++) {
        int t = t0 + i;
        float4 v;
        v.x = (st0 == t) ? 1.0f : 0.0f;
        v.y = (st1 == t) ? 1.0f : 0.0f;
        v.z = (st2 == t) ? 1.0f : 0.0f;
        v.w = (st3 == t) ? 1.0f : 0.0f;
        __stcs(p, v);          // streaming store, evict-first
        p += stride4;
    }
}

// Generic-T fallback (single split, dynamic trip count)
__global__ void __launch_bounds__(256)
temporal_encode_fused_dyn(const float4* __restrict__ in,
                          float4* __restrict__ out,
                          int BN4, int T)
{
    int idx = blockIdx.x * blockDim.x + threadIdx.x;
    if (idx >= BN4) return;

    float4 x = in[idx];
    const float tm1 = (float)(T - 1);
    int st0 = xla_spike_time(x.x, tm1);
    int st1 = xla_spike_time(x.y, tm1);
    int st2 = xla_spike_time(x.z, tm1);
    int st3 = xla_spike_time(x.w, tm1);

    float4* p = out + idx;
    const size_t stride4 = (size_t)BN4;
#pragma unroll 4
    for (int t = 0; t < T; t++) {
        float4 v;
        v.x = (st0 == t) ? 1.0f : 0.0f;
        v.y = (st1 == t) ? 1.0f : 0.0f;
        v.z = (st2 == t) ? 1.0f : 0.0f;
        v.w = (st3 == t) ? 1.0f : 0.0f;
        __stcs(p, v);
        p += stride4;
    }
}

extern "C" void kernel_launch(void* const* d_in, const int* in_sizes, int n_in,
                              void* d_out, int out_size)
{
    const float* in = (const float*)d_in[0];
    float4* out = (float4*)d_out;

    const int BN = in_sizes[0];   // B * N = 1048576
    const int T = out_size / BN;  // timesteps = 100
    const int BN4 = BN / 4;

    const int threads = 256;
    const int cblocks = (BN4 + threads - 1) / threads;

    if (T == 100) {
        dim3 grid(cblocks, 4);    // 1024 x 4 = 4096 blocks, 25 planes each
        temporal_encode_fused<100, 4><<<grid, threads>>>(
            (const float4*)in, out, BN4);
    } else {
        temporal_encode_fused_dyn<<<cblocks, threads>>>(
            (const float4*)in, out, BN4, T);
    }
}